// round 1
// baseline (speedup 1.0000x reference)
#include <cuda_runtime.h>
#include <math.h>
#include <float.h>

#define BB 8
#define CC 512
#define LL 8192
#define HH 8
#define DD 64

// Scratch (static device globals: allocation-free per harness rules)
static __device__ float g_Q[(size_t)BB * CC * LL];
static __device__ float g_K[(size_t)BB * CC * LL];
static __device__ float g_V[(size_t)BB * CC * LL];
static __device__ float g_ATT[(size_t)BB * CC * LL];
static __device__ float g_CTX[BB * HH * DD * DD];

// ---------------------------------------------------------------------------
// GEMM: Y[b,o,l] = sum_c W[o,c] * X[b,c,l] + bias[o] (+ resid[b,o,l])
// 128x128 block tile, BK=16, 256 threads, 8x8 microtile.
// ---------------------------------------------------------------------------
__global__ __launch_bounds__(256, 2) void gemm_kernel(
    const float* __restrict__ W, const float* __restrict__ bias,
    const float* __restrict__ X, const float* __restrict__ resid,
    float* __restrict__ Y)
{
    const int b = blockIdx.z;
    const int oTile = blockIdx.y * 128;
    const int lTile = blockIdx.x * 128;
    const float* Xb = X + (size_t)b * CC * LL;

    __shared__ float Ws[16][128];   // [k][m]
    __shared__ float Xs[16][128];   // [k][n]

    float acc[8][8];
#pragma unroll
    for (int i = 0; i < 8; i++)
#pragma unroll
        for (int j = 0; j < 8; j++) acc[i][j] = 0.f;

    const int tid = threadIdx.x;
    const int tm = (tid >> 4) * 8;
    const int tn = (tid & 15) * 8;
    const int wRow = tid >> 2;          // 0..63
    const int wCol = (tid & 3) * 4;     // 0,4,8,12
    const int xRow = tid >> 5;          // 0..7
    const int xCol = (tid & 31) * 4;

    for (int k0 = 0; k0 < CC; k0 += 16) {
#pragma unroll
        for (int i = 0; i < 2; i++) {
            const int row = wRow + i * 64;
            const float4 w4 = *(const float4*)(W + (size_t)(oTile + row) * CC + k0 + wCol);
            Ws[wCol + 0][row] = w4.x;
            Ws[wCol + 1][row] = w4.y;
            Ws[wCol + 2][row] = w4.z;
            Ws[wCol + 3][row] = w4.w;
        }
#pragma unroll
        for (int i = 0; i < 2; i++) {
            const int row = xRow + i * 8;
            *(float4*)(&Xs[row][xCol]) =
                *(const float4*)(Xb + (size_t)(k0 + row) * LL + lTile + xCol);
        }
        __syncthreads();
#pragma unroll
        for (int k = 0; k < 16; k++) {
            float a[8], bv[8];
#pragma unroll
            for (int i = 0; i < 8; i += 4)
                *(float4*)&a[i] = *(const float4*)&Ws[k][tm + i];
#pragma unroll
            for (int j = 0; j < 8; j += 4)
                *(float4*)&bv[j] = *(const float4*)&Xs[k][tn + j];
#pragma unroll
            for (int i = 0; i < 8; i++)
#pragma unroll
                for (int j = 0; j < 8; j++)
                    acc[i][j] = fmaf(a[i], bv[j], acc[i][j]);
        }
        __syncthreads();
    }

#pragma unroll
    for (int i = 0; i < 8; i++) {
        const int o = oTile + tm + i;
        const float bb = bias[o];
        float* yrow = Y + (size_t)b * CC * LL + (size_t)o * LL + lTile;
#pragma unroll
        for (int j = 0; j < 8; j += 4) {
            float4 v;
            v.x = acc[i][j + 0] + bb;
            v.y = acc[i][j + 1] + bb;
            v.z = acc[i][j + 2] + bb;
            v.w = acc[i][j + 3] + bb;
            if (resid) {
                const float4 r = *(const float4*)(resid + (size_t)b * CC * LL +
                                                  (size_t)o * LL + lTile + tn + j);
                v.x += r.x; v.y += r.y; v.z += r.z; v.w += r.w;
            }
            *(float4*)(yrow + tn + j) = v;
        }
    }
}

// ---------------------------------------------------------------------------
// Softmax over L (axis=3): one block per (b, c) row of length LL.
// ---------------------------------------------------------------------------
__global__ __launch_bounds__(256) void softmax_l_kernel(float* __restrict__ P)
{
    float* p = P + (size_t)blockIdx.x * LL;
    const int tid = threadIdx.x;
    float v[LL / 256];
    float m = -FLT_MAX;
#pragma unroll
    for (int i = 0; i < LL / 256; i++) {
        v[i] = p[tid + i * 256];
        m = fmaxf(m, v[i]);
    }
    __shared__ float red[256];
    red[tid] = m; __syncthreads();
    for (int s = 128; s > 0; s >>= 1) {
        if (tid < s) red[tid] = fmaxf(red[tid], red[tid + s]);
        __syncthreads();
    }
    m = red[0];
    __syncthreads();
    float sum = 0.f;
#pragma unroll
    for (int i = 0; i < LL / 256; i++) {
        v[i] = __expf(v[i] - m);
        sum += v[i];
    }
    red[tid] = sum; __syncthreads();
    for (int s = 128; s > 0; s >>= 1) {
        if (tid < s) red[tid] += red[tid + s];
        __syncthreads();
    }
    const float inv = 1.f / red[0];
#pragma unroll
    for (int i = 0; i < LL / 256; i++) p[tid + i * 256] = v[i] * inv;
}

// ---------------------------------------------------------------------------
// Softmax over DK (axis=2): each thread owns one l; 64 channels in registers.
// grid: (LL/256, HH, BB)
// ---------------------------------------------------------------------------
__global__ __launch_bounds__(256) void softmax_d_kernel(float* __restrict__ P)
{
    const int l = blockIdx.x * 256 + threadIdx.x;
    float* p = P + ((size_t)blockIdx.z * CC + blockIdx.y * DD) * LL + l;
    float v[DD];
    float m = -FLT_MAX;
#pragma unroll
    for (int d = 0; d < DD; d++) {
        v[d] = p[(size_t)d * LL];
        m = fmaxf(m, v[d]);
    }
    float s = 0.f;
#pragma unroll
    for (int d = 0; d < DD; d++) {
        v[d] = __expf(v[d] - m);
        s += v[d];
    }
    const float inv = 1.f / s;
#pragma unroll
    for (int d = 0; d < DD; d++) p[(size_t)d * LL] = v[d] * inv;
}

// ---------------------------------------------------------------------------
// Zero the ctx accumulator.
// ---------------------------------------------------------------------------
__global__ void zero_ctx_kernel(float* __restrict__ C)
{
    C[blockIdx.x * 256 + threadIdx.x] = 0.f;
}

// ---------------------------------------------------------------------------
// ctx[b,h,dk,dv] = sum_l K[b,h*64+dk,l] * V[b,h*64+dv,l]
// grid: (SPLIT=16, HH, BB), 128 threads, 8x4 microtile, atomic accumulate.
// ---------------------------------------------------------------------------
__global__ __launch_bounds__(128) void ctx_kernel(
    const float* __restrict__ Kk, const float* __restrict__ Vv,
    float* __restrict__ CTX)
{
    const int b = blockIdx.z, h = blockIdx.y;
    const int lStart = blockIdx.x * (LL / 16);   // 512 per block
    const float* kp = Kk + ((size_t)b * CC + h * DD) * LL;
    const float* vp = Vv + ((size_t)b * CC + h * DD) * LL;

    __shared__ float ks[32][65];   // [l][dk], pad 65 -> conflict-free transpose
    __shared__ float vs[32][65];   // [l][dv]

    const int dk0 = (threadIdx.x >> 4) * 8;   // 0..56
    const int dv0 = (threadIdx.x & 15) * 4;   // 0..60
    float acc[8][4];
#pragma unroll
    for (int i = 0; i < 8; i++)
#pragma unroll
        for (int j = 0; j < 4; j++) acc[i][j] = 0.f;

    for (int t = 0; t < LL / 16; t += 32) {
#pragma unroll
        for (int i = 0; i < 4; i++) {
            const int idx = threadIdx.x + i * 128;   // 0..511
            const int row = idx >> 3;                // 0..63 (channel)
            const int col = (idx & 7) * 4;           // 0..28 (l within chunk)
            const float4 k4 = *(const float4*)(kp + (size_t)row * LL + lStart + t + col);
            ks[col + 0][row] = k4.x; ks[col + 1][row] = k4.y;
            ks[col + 2][row] = k4.z; ks[col + 3][row] = k4.w;
            const float4 v4 = *(const float4*)(vp + (size_t)row * LL + lStart + t + col);
            vs[col + 0][row] = v4.x; vs[col + 1][row] = v4.y;
            vs[col + 2][row] = v4.z; vs[col + 3][row] = v4.w;
        }
        __syncthreads();
#pragma unroll 8
        for (int ll = 0; ll < 32; ll++) {
            float a[8], bq[4];
#pragma unroll
            for (int i = 0; i < 8; i++) a[i] = ks[ll][dk0 + i];
#pragma unroll
            for (int j = 0; j < 4; j++) bq[j] = vs[ll][dv0 + j];
#pragma unroll
            for (int i = 0; i < 8; i++)
#pragma unroll
                for (int j = 0; j < 4; j++)
                    acc[i][j] = fmaf(a[i], bq[j], acc[i][j]);
        }
        __syncthreads();
    }

    float* cp = CTX + (size_t)(b * HH + h) * DD * DD;
#pragma unroll
    for (int i = 0; i < 8; i++)
#pragma unroll
        for (int j = 0; j < 4; j++)
            atomicAdd(&cp[(dk0 + i) * DD + dv0 + j], acc[i][j]);
}

// ---------------------------------------------------------------------------
// att[b, h*64+dv, l] = sum_dk ctx[b,h,dk,dv] * Q[b, h*64+dk, l]
// grid: (LL/128, HH, BB), 128 threads; thread = 16 dv x 4 l.
// ---------------------------------------------------------------------------
__global__ __launch_bounds__(128) void att_kernel(
    const float* __restrict__ Q, const float* __restrict__ CTX,
    float* __restrict__ ATT)
{
    const int b = blockIdx.z, h = blockIdx.y;
    const int lBase = blockIdx.x * 128;

    __shared__ float cs[DD][DD];   // [dk][dv]
    const float* cp = CTX + (size_t)(b * HH + h) * DD * DD;
    for (int i = threadIdx.x; i < DD * DD; i += 128)
        ((float*)cs)[i] = cp[i];
    __syncthreads();

    const int dv0 = (threadIdx.x >> 5) * 16;           // warp-uniform -> smem broadcast
    const int l0 = lBase + (threadIdx.x & 31) * 4;
    const float* qp = Q + ((size_t)b * CC + h * DD) * LL;

    float acc[16][4];
#pragma unroll
    for (int j = 0; j < 16; j++)
#pragma unroll
        for (int i = 0; i < 4; i++) acc[j][i] = 0.f;

#pragma unroll 4
    for (int dk = 0; dk < DD; dk++) {
        const float4 q4 = *(const float4*)(qp + (size_t)dk * LL + l0);
#pragma unroll
        for (int j = 0; j < 16; j++) {
            const float c = cs[dk][dv0 + j];
            acc[j][0] = fmaf(c, q4.x, acc[j][0]);
            acc[j][1] = fmaf(c, q4.y, acc[j][1]);
            acc[j][2] = fmaf(c, q4.z, acc[j][2]);
            acc[j][3] = fmaf(c, q4.w, acc[j][3]);
        }
    }

    float* ap = ATT + ((size_t)b * CC + h * DD) * LL;
#pragma unroll
    for (int j = 0; j < 16; j++) {
        float4 v;
        v.x = acc[j][0]; v.y = acc[j][1]; v.z = acc[j][2]; v.w = acc[j][3];
        *(float4*)(ap + (size_t)(dv0 + j) * LL + l0) = v;
    }
}

// ---------------------------------------------------------------------------
extern "C" void kernel_launch(void* const* d_in, const int* in_sizes, int n_in,
                              void* d_out, int out_size)
{
    const float* input_ = (const float*)d_in[0];
    const float* context_ = (const float*)d_in[1];
    const float* Wk = (const float*)d_in[2];
    const float* bk = (const float*)d_in[3];
    const float* Wq = (const float*)d_in[4];
    const float* bq = (const float*)d_in[5];
    const float* Wv = (const float*)d_in[6];
    const float* bv = (const float*)d_in[7];
    const float* Wr = (const float*)d_in[8];
    const float* br = (const float*)d_in[9];
    float* out = (float*)d_out;

    float *Qp, *Kp, *Vp, *Ap, *Cp;
    cudaGetSymbolAddress((void**)&Qp, g_Q);
    cudaGetSymbolAddress((void**)&Kp, g_K);
    cudaGetSymbolAddress((void**)&Vp, g_V);
    cudaGetSymbolAddress((void**)&Ap, g_ATT);
    cudaGetSymbolAddress((void**)&Cp, g_CTX);

    const dim3 gGemm(LL / 128, CC / 128, BB);

    gemm_kernel<<<gGemm, 256>>>(Wq, bq, input_, nullptr, Qp);
    gemm_kernel<<<gGemm, 256>>>(Wk, bk, context_, nullptr, Kp);
    gemm_kernel<<<gGemm, 256>>>(Wv, bv, context_, nullptr, Vp);

    softmax_l_kernel<<<BB * CC, 256>>>(Kp);
    softmax_d_kernel<<<dim3(LL / 256, HH, BB), 256>>>(Qp);

    zero_ctx_kernel<<<(BB * HH * DD * DD) / 256, 256>>>(Cp);
    ctx_kernel<<<dim3(16, HH, BB), 128>>>(Kp, Vp, Cp);
    att_kernel<<<dim3(LL / 128, HH, BB), 128>>>(Qp, Cp, Ap);

    gemm_kernel<<<gGemm, 256>>>(Wr, br, Ap, input_, out);
}

// round 3
// speedup vs baseline: 1.8142x; 1.8142x over previous
#include <cuda_runtime.h>
#include <cuda_bf16.h>
#include <math.h>
#include <float.h>
#include <stdint.h>

#define BB 8
#define CC 512
#define LL 8192
#define HH 8
#define DD 64

// ---------------------------------------------------------------------------
// Scratch (static device globals: allocation-free per harness rules)
// ---------------------------------------------------------------------------
static __device__ float g_Q[(size_t)BB * CC * LL];
static __device__ float g_K[(size_t)BB * CC * LL];
static __device__ float g_V[(size_t)BB * CC * LL];
static __device__ float g_ATT[(size_t)BB * CC * LL];
static __device__ float g_CTX[BB * HH * DD * DD];

// transposed bf16 hi/lo operands: [B][L][C], C contiguous (K-contiguous for MMA B)
static __device__ __align__(256) __nv_bfloat16 g_Bh_in[(size_t)BB * LL * CC];
static __device__ __align__(256) __nv_bfloat16 g_Bl_in[(size_t)BB * LL * CC];
static __device__ __align__(256) __nv_bfloat16 g_Bh_ctx[(size_t)BB * LL * CC];
static __device__ __align__(256) __nv_bfloat16 g_Bl_ctx[(size_t)BB * LL * CC];
static __device__ __align__(256) __nv_bfloat16 g_Bh_att[(size_t)BB * LL * CC];
static __device__ __align__(256) __nv_bfloat16 g_Bl_att[(size_t)BB * LL * CC];
// weights bf16 hi/lo: 0=q 1=k 2=v 3=r   ([O][C] row-major, K-contiguous)
static __device__ __align__(256) __nv_bfloat16 g_Wh[4][CC * CC];
static __device__ __align__(256) __nv_bfloat16 g_Wl[4][CC * CC];

// ---------------------------------------------------------------------------
__device__ __forceinline__ uint32_t smem_u32(const void* p) {
    uint32_t a;
    asm("{ .reg .u64 t; cvta.to.shared.u64 t, %1; cvt.u32.u64 %0, t; }"
        : "=r"(a) : "l"(p));
    return a;
}
__device__ __forceinline__ void ldm_x4(uint32_t* r, uint32_t addr) {
    asm volatile("ldmatrix.sync.aligned.m8n8.x4.shared.b16 {%0,%1,%2,%3}, [%4];"
                 : "=r"(r[0]), "=r"(r[1]), "=r"(r[2]), "=r"(r[3]) : "r"(addr));
}
__device__ __forceinline__ void ldm_x2(uint32_t* r, uint32_t addr) {
    asm volatile("ldmatrix.sync.aligned.m8n8.x2.shared.b16 {%0,%1}, [%2];"
                 : "=r"(r[0]), "=r"(r[1]) : "r"(addr));
}
__device__ __forceinline__ void mma_bf16(float* d, const uint32_t* a, const uint32_t* b) {
    asm volatile(
        "mma.sync.aligned.m16n8k16.row.col.f32.bf16.bf16.f32 "
        "{%0,%1,%2,%3}, {%4,%5,%6,%7}, {%8,%9}, {%0,%1,%2,%3};"
        : "+f"(d[0]), "+f"(d[1]), "+f"(d[2]), "+f"(d[3])
        : "r"(a[0]), "r"(a[1]), "r"(a[2]), "r"(a[3]), "r"(b[0]), "r"(b[1]));
}

// ---------------------------------------------------------------------------
// Weight convert: fp32 [O,C] -> bf16 hi + lo
// ---------------------------------------------------------------------------
__global__ void wconv_kernel(const float* __restrict__ W,
                             __nv_bfloat16* __restrict__ Wh,
                             __nv_bfloat16* __restrict__ Wl)
{
    const int i = blockIdx.x * 256 + threadIdx.x;
    const float x = W[i];
    const __nv_bfloat16 hi = __float2bfloat16(x);
    Wh[i] = hi;
    Wl[i] = __float2bfloat16(x - __bfloat162float(hi));
}

// ---------------------------------------------------------------------------
// Transpose + split: X[b][c][l] fp32 -> XT[b][l][c] bf16 hi/lo
// grid (L/32, C/32, B), block (32, 8)
// ---------------------------------------------------------------------------
__global__ __launch_bounds__(256) void tconv_kernel(
    const float* __restrict__ X,
    __nv_bfloat16* __restrict__ Th, __nv_bfloat16* __restrict__ Tl)
{
    __shared__ float t[32][33];
    const int l0 = blockIdx.x * 32, c0 = blockIdx.y * 32, b = blockIdx.z;
    const float* xp = X + ((size_t)b * CC + c0) * LL + l0;
#pragma unroll
    for (int i = 0; i < 4; i++) {
        const int c = threadIdx.y + i * 8;
        t[c][threadIdx.x] = xp[(size_t)c * LL + threadIdx.x];
    }
    __syncthreads();
    __nv_bfloat16* th = Th + ((size_t)b * LL + l0) * CC + c0;
    __nv_bfloat16* tl = Tl + ((size_t)b * LL + l0) * CC + c0;
#pragma unroll
    for (int i = 0; i < 4; i++) {
        const int row = threadIdx.y + i * 8;
        const float v = t[threadIdx.x][row];
        const __nv_bfloat16 hi = __float2bfloat16(v);
        th[(size_t)row * CC + threadIdx.x] = hi;
        tl[(size_t)row * CC + threadIdx.x] =
            __float2bfloat16(v - __bfloat162float(hi));
    }
}

// ---------------------------------------------------------------------------
// mma.sync bf16 GEMM (3-term split):
//   Y[b, m0+m, n0+n] = sum_c A[m][c]*B[b][n][c] + bias (+resid)
// CTA tile M=128 N=128 K=32; 8 warps (2m x 4n); warp tile 64x32 (m16n8k16).
// smem rows padded to 40 halves (80B) -> conflict-free ldmatrix.
// ---------------------------------------------------------------------------
#define PADK 40
#define NCHUNK (CC / 32)

__global__ void __launch_bounds__(256, 1) gemm_mma_kernel(
    const __nv_bfloat16* __restrict__ Ah, const __nv_bfloat16* __restrict__ Al,
    const __nv_bfloat16* __restrict__ Bh, const __nv_bfloat16* __restrict__ Bl,
    const float* __restrict__ bias, const float* __restrict__ resid,
    float* __restrict__ Y)
{
    __shared__ __nv_bfloat16 sAh[128 * PADK], sAl[128 * PADK];
    __shared__ __nv_bfloat16 sBh[128 * PADK], sBl[128 * PADK];

    const int tid = threadIdx.x, lane = tid & 31, wid = tid >> 5;
    const int wm = wid >> 2, wn = wid & 3;
    const int b = blockIdx.z;
    const int n0 = blockIdx.x * 128;
    const int m0 = blockIdx.y * 128;

    const __nv_bfloat16* Arh = Ah + (size_t)m0 * CC;
    const __nv_bfloat16* Arl = Al + (size_t)m0 * CC;
    const __nv_bfloat16* Brh = Bh + ((size_t)b * LL + n0) * CC;
    const __nv_bfloat16* Brl = Bl + ((size_t)b * LL + n0) * CC;

    // loader: element e = tid + t*256 -> row e>>2 (0..127), 16B group e&3
    const int ldRow = tid >> 2;
    const int ldC16 = (tid & 3) * 8;          // halves
    const size_t gOffBase = (size_t)ldRow * CC + ldC16;
    const uint32_t sOff = (uint32_t)(ldRow * PADK + ldC16);   // halves

    float acc[4][4][4];
#pragma unroll
    for (int i = 0; i < 4; i++)
#pragma unroll
        for (int j = 0; j < 4; j++)
#pragma unroll
            for (int x = 0; x < 4; x++) acc[i][j][x] = 0.f;

    // load chunk 0
#pragma unroll
    for (int t = 0; t < 2; t++) {
        const size_t go = gOffBase + (size_t)t * 64 * CC;
        const uint32_t so = sOff + t * 64 * PADK;
        *(uint4*)(sAh + so) = *(const uint4*)(Arh + go);
        *(uint4*)(sAl + so) = *(const uint4*)(Arl + go);
        *(uint4*)(sBh + so) = *(const uint4*)(Brh + go);
        *(uint4*)(sBl + so) = *(const uint4*)(Brl + go);
    }

    // ldmatrix smem byte addresses
    const uint32_t aRow = (uint32_t)(wm * 64) + (lane & 7) + (lane & 8);
    const uint32_t aKh = (lane & 16) >> 1;                    // +0 / +8 halves
    const uint32_t aOffB = (aRow * PADK + aKh) * 2;           // bytes (per mt: +16*PADK*2; per kstep: +32B)
    const uint32_t bRow = (uint32_t)(wn * 32) + (lane & 7);
    const uint32_t bKh = (uint32_t)(lane & 8);
    const uint32_t bOffB = (bRow * PADK + bKh) * 2;
    const uint32_t sAh32 = smem_u32(sAh), sAl32 = smem_u32(sAl);
    const uint32_t sBh32 = smem_u32(sBh), sBl32 = smem_u32(sBl);

    uint4 pA0, pA1, pB0, pB1, pC0, pC1, pD0, pD1;

    for (int kc = 0; kc < NCHUNK; kc++) {
        __syncthreads();
        if (kc + 1 < NCHUNK) {
            const size_t gk = gOffBase + (size_t)(kc + 1) * 32;
            pA0 = *(const uint4*)(Arh + gk);
            pA1 = *(const uint4*)(Arh + gk + (size_t)64 * CC);
            pB0 = *(const uint4*)(Arl + gk);
            pB1 = *(const uint4*)(Arl + gk + (size_t)64 * CC);
            pC0 = *(const uint4*)(Brh + gk);
            pC1 = *(const uint4*)(Brh + gk + (size_t)64 * CC);
            pD0 = *(const uint4*)(Brl + gk);
            pD1 = *(const uint4*)(Brl + gk + (size_t)64 * CC);
        }
#pragma unroll
        for (int ks = 0; ks < 2; ks++) {
            const uint32_t kb = ks * 32;   // bytes: 16 halves
            uint32_t fah[4][4], fal[4][4], fbh[4][2], fbl[4][2];
#pragma unroll
            for (int mt = 0; mt < 4; mt++) {
                const uint32_t o = aOffB + mt * (16 * PADK * 2) + kb;
                ldm_x4(fah[mt], sAh32 + o);
                ldm_x4(fal[mt], sAl32 + o);
            }
#pragma unroll
            for (int nt = 0; nt < 4; nt++) {
                const uint32_t o = bOffB + nt * (8 * PADK * 2) + kb;
                ldm_x2(fbh[nt], sBh32 + o);
                ldm_x2(fbl[nt], sBl32 + o);
            }
#pragma unroll
            for (int mt = 0; mt < 4; mt++)
#pragma unroll
                for (int nt = 0; nt < 4; nt++) {
                    mma_bf16(acc[mt][nt], fah[mt], fbh[nt]);
                    mma_bf16(acc[mt][nt], fah[mt], fbl[nt]);
                    mma_bf16(acc[mt][nt], fal[mt], fbh[nt]);
                }
        }
        __syncthreads();
        if (kc + 1 < NCHUNK) {
            *(uint4*)(sAh + sOff) = pA0;
            *(uint4*)(sAh + sOff + 64 * PADK) = pA1;
            *(uint4*)(sAl + sOff) = pB0;
            *(uint4*)(sAl + sOff + 64 * PADK) = pB1;
            *(uint4*)(sBh + sOff) = pC0;
            *(uint4*)(sBh + sOff + 64 * PADK) = pC1;
            *(uint4*)(sBl + sOff) = pD0;
            *(uint4*)(sBl + sOff + 64 * PADK) = pD1;
        }
    }

    // epilogue
    const int mbase = m0 + wm * 64 + (lane >> 2);
    const int nbase = n0 + wn * 32 + (lane & 3) * 2;
#pragma unroll
    for (int mt = 0; mt < 4; mt++) {
        const int m = mbase + mt * 16;
        const float bv0 = bias[m], bv1 = bias[m + 8];
        float* y0 = Y + ((size_t)b * CC + m) * LL;
        float* y1 = y0 + (size_t)8 * LL;
        const float* r0 = resid ? resid + ((size_t)b * CC + m) * LL : (const float*)0;
#pragma unroll
        for (int nt = 0; nt < 4; nt++) {
            const int n = nbase + nt * 8;
            float2 v0, v1;
            v0.x = acc[mt][nt][0] + bv0;
            v0.y = acc[mt][nt][1] + bv0;
            v1.x = acc[mt][nt][2] + bv1;
            v1.y = acc[mt][nt][3] + bv1;
            if (r0) {
                const float2 q0 = *(const float2*)(r0 + n);
                const float2 q1 = *(const float2*)(r0 + (size_t)8 * LL + n);
                v0.x += q0.x; v0.y += q0.y;
                v1.x += q1.x; v1.y += q1.y;
            }
            *(float2*)(y0 + n) = v0;
            *(float2*)(y1 + n) = v1;
        }
    }
}

// ---------------------------------------------------------------------------
// Softmax over L (axis=3): one block per (b, c) row.
// ---------------------------------------------------------------------------
__global__ __launch_bounds__(256) void softmax_l_kernel(float* __restrict__ P)
{
    float* p = P + (size_t)blockIdx.x * LL;
    const int tid = threadIdx.x;
    float v[LL / 256];
    float m = -FLT_MAX;
#pragma unroll
    for (int i = 0; i < LL / 256; i++) {
        v[i] = p[tid + i * 256];
        m = fmaxf(m, v[i]);
    }
    __shared__ float red[256];
    red[tid] = m; __syncthreads();
    for (int s = 128; s > 0; s >>= 1) {
        if (tid < s) red[tid] = fmaxf(red[tid], red[tid + s]);
        __syncthreads();
    }
    m = red[0];
    __syncthreads();
    float sum = 0.f;
#pragma unroll
    for (int i = 0; i < LL / 256; i++) {
        v[i] = __expf(v[i] - m);
        sum += v[i];
    }
    red[tid] = sum; __syncthreads();
    for (int s = 128; s > 0; s >>= 1) {
        if (tid < s) red[tid] += red[tid + s];
        __syncthreads();
    }
    const float inv = 1.f / red[0];
#pragma unroll
    for (int i = 0; i < LL / 256; i++) p[tid + i * 256] = v[i] * inv;
}

// ---------------------------------------------------------------------------
// Softmax over DK (axis=2).
// ---------------------------------------------------------------------------
__global__ __launch_bounds__(256) void softmax_d_kernel(float* __restrict__ P)
{
    const int l = blockIdx.x * 256 + threadIdx.x;
    float* p = P + ((size_t)blockIdx.z * CC + blockIdx.y * DD) * LL + l;
    float v[DD];
    float m = -FLT_MAX;
#pragma unroll
    for (int d = 0; d < DD; d++) {
        v[d] = p[(size_t)d * LL];
        m = fmaxf(m, v[d]);
    }
    float s = 0.f;
#pragma unroll
    for (int d = 0; d < DD; d++) {
        v[d] = __expf(v[d] - m);
        s += v[d];
    }
    const float inv = 1.f / s;
#pragma unroll
    for (int d = 0; d < DD; d++) p[(size_t)d * LL] = v[d] * inv;
}

__global__ void zero_ctx_kernel(float* __restrict__ C)
{
    C[blockIdx.x * 256 + threadIdx.x] = 0.f;
}

// ---------------------------------------------------------------------------
// ctx[b,h,dk,dv] = sum_l K[b,h*64+dk,l] * V[b,h*64+dv,l]
// ---------------------------------------------------------------------------
__global__ __launch_bounds__(128) void ctx_kernel(
    const float* __restrict__ Kk, const float* __restrict__ Vv,
    float* __restrict__ CTX)
{
    const int b = blockIdx.z, h = blockIdx.y;
    const int lStart = blockIdx.x * (LL / 16);
    const float* kp = Kk + ((size_t)b * CC + h * DD) * LL;
    const float* vp = Vv + ((size_t)b * CC + h * DD) * LL;

    __shared__ float ks[32][65];
    __shared__ float vs[32][65];

    const int dk0 = (threadIdx.x >> 4) * 8;
    const int dv0 = (threadIdx.x & 15) * 4;
    float acc[8][4];
#pragma unroll
    for (int i = 0; i < 8; i++)
#pragma unroll
        for (int j = 0; j < 4; j++) acc[i][j] = 0.f;

    for (int t = 0; t < LL / 16; t += 32) {
#pragma unroll
        for (int i = 0; i < 4; i++) {
            const int idx = threadIdx.x + i * 128;
            const int row = idx >> 3;
            const int col = (idx & 7) * 4;
            const float4 k4 = *(const float4*)(kp + (size_t)row * LL + lStart + t + col);
            ks[col + 0][row] = k4.x; ks[col + 1][row] = k4.y;
            ks[col + 2][row] = k4.z; ks[col + 3][row] = k4.w;
            const float4 v4 = *(const float4*)(vp + (size_t)row * LL + lStart + t + col);
            vs[col + 0][row] = v4.x; vs[col + 1][row] = v4.y;
            vs[col + 2][row] = v4.z; vs[col + 3][row] = v4.w;
        }
        __syncthreads();
#pragma unroll 8
        for (int ll = 0; ll < 32; ll++) {
            float a[8], bq[4];
#pragma unroll
            for (int i = 0; i < 8; i++) a[i] = ks[ll][dk0 + i];
#pragma unroll
            for (int j = 0; j < 4; j++) bq[j] = vs[ll][dv0 + j];
#pragma unroll
            for (int i = 0; i < 8; i++)
#pragma unroll
                for (int j = 0; j < 4; j++)
                    acc[i][j] = fmaf(a[i], bq[j], acc[i][j]);
        }
        __syncthreads();
    }

    float* cp = CTX + (size_t)(b * HH + h) * DD * DD;
#pragma unroll
    for (int i = 0; i < 8; i++)
#pragma unroll
        for (int j = 0; j < 4; j++)
            atomicAdd(&cp[(dk0 + i) * DD + dv0 + j], acc[i][j]);
}

// ---------------------------------------------------------------------------
// att[b, h*64+dv, l] = sum_dk ctx[b,h,dk,dv] * Q[b, h*64+dk, l]
// ---------------------------------------------------------------------------
__global__ __launch_bounds__(128) void att_kernel(
    const float* __restrict__ Q, const float* __restrict__ CTX,
    float* __restrict__ ATT)
{
    const int b = blockIdx.z, h = blockIdx.y;
    const int lBase = blockIdx.x * 128;

    __shared__ float cs[DD][DD];
    const float* cp = CTX + (size_t)(b * HH + h) * DD * DD;
    for (int i = threadIdx.x; i < DD * DD; i += 128)
        ((float*)cs)[i] = cp[i];
    __syncthreads();

    const int dv0 = (threadIdx.x >> 5) * 16;
    const int l0 = lBase + (threadIdx.x & 31) * 4;
    const float* qp = Q + ((size_t)b * CC + h * DD) * LL;

    float acc[16][4];
#pragma unroll
    for (int j = 0; j < 16; j++)
#pragma unroll
        for (int i = 0; i < 4; i++) acc[j][i] = 0.f;

#pragma unroll 4
    for (int dk = 0; dk < DD; dk++) {
        const float4 q4 = *(const float4*)(qp + (size_t)dk * LL + l0);
#pragma unroll
        for (int j = 0; j < 16; j++) {
            const float c = cs[dk][dv0 + j];
            acc[j][0] = fmaf(c, q4.x, acc[j][0]);
            acc[j][1] = fmaf(c, q4.y, acc[j][1]);
            acc[j][2] = fmaf(c, q4.z, acc[j][2]);
            acc[j][3] = fmaf(c, q4.w, acc[j][3]);
        }
    }

    float* ap = ATT + ((size_t)b * CC + h * DD) * LL;
#pragma unroll
    for (int j = 0; j < 16; j++) {
        float4 v;
        v.x = acc[j][0]; v.y = acc[j][1]; v.z = acc[j][2]; v.w = acc[j][3];
        *(float4*)(ap + (size_t)(dv0 + j) * LL + l0) = v;
    }
}

// ---------------------------------------------------------------------------
extern "C" void kernel_launch(void* const* d_in, const int* in_sizes, int n_in,
                              void* d_out, int out_size)
{
    const float* input_ = (const float*)d_in[0];
    const float* context_ = (const float*)d_in[1];
    const float* Wk = (const float*)d_in[2];
    const float* bk = (const float*)d_in[3];
    const float* Wq = (const float*)d_in[4];
    const float* bq = (const float*)d_in[5];
    const float* Wv = (const float*)d_in[6];
    const float* bv = (const float*)d_in[7];
    const float* Wr = (const float*)d_in[8];
    const float* br = (const float*)d_in[9];
    float* out = (float*)d_out;

    float *Qp, *Kp, *Vp, *Ap, *Cp;
    cudaGetSymbolAddress((void**)&Qp, g_Q);
    cudaGetSymbolAddress((void**)&Kp, g_K);
    cudaGetSymbolAddress((void**)&Vp, g_V);
    cudaGetSymbolAddress((void**)&Ap, g_ATT);
    cudaGetSymbolAddress((void**)&Cp, g_CTX);

    __nv_bfloat16 *BhIn, *BlIn, *BhCtx, *BlCtx, *BhAtt, *BlAtt, *Wh, *Wl;
    cudaGetSymbolAddress((void**)&BhIn, g_Bh_in);
    cudaGetSymbolAddress((void**)&BlIn, g_Bl_in);
    cudaGetSymbolAddress((void**)&BhCtx, g_Bh_ctx);
    cudaGetSymbolAddress((void**)&BlCtx, g_Bl_ctx);
    cudaGetSymbolAddress((void**)&BhAtt, g_Bh_att);
    cudaGetSymbolAddress((void**)&BlAtt, g_Bl_att);
    cudaGetSymbolAddress((void**)&Wh, g_Wh);
    cudaGetSymbolAddress((void**)&Wl, g_Wl);

    // weight conversions (0=q 1=k 2=v 3=r)
    wconv_kernel<<<CC * CC / 256, 256>>>(Wq, Wh + 0 * CC * CC, Wl + 0 * CC * CC);
    wconv_kernel<<<CC * CC / 256, 256>>>(Wk, Wh + 1 * CC * CC, Wl + 1 * CC * CC);
    wconv_kernel<<<CC * CC / 256, 256>>>(Wv, Wh + 2 * CC * CC, Wl + 2 * CC * CC);
    wconv_kernel<<<CC * CC / 256, 256>>>(Wr, Wh + 3 * CC * CC, Wl + 3 * CC * CC);

    // input transposes + bf16 split
    const dim3 gT(LL / 32, CC / 32, BB);
    tconv_kernel<<<gT, dim3(32, 8)>>>(input_, BhIn, BlIn);
    tconv_kernel<<<gT, dim3(32, 8)>>>(context_, BhCtx, BlCtx);

    // projections on tensor cores (mma.sync bf16, 3-term split)
    const dim3 gG(LL / 128, CC / 128, BB);
    gemm_mma_kernel<<<gG, 256>>>(Wh + 0 * CC * CC, Wl + 0 * CC * CC,
                                 BhIn, BlIn, bq, nullptr, Qp);
    gemm_mma_kernel<<<gG, 256>>>(Wh + 1 * CC * CC, Wl + 1 * CC * CC,
                                 BhCtx, BlCtx, bk, nullptr, Kp);
    gemm_mma_kernel<<<gG, 256>>>(Wh + 2 * CC * CC, Wl + 2 * CC * CC,
                                 BhCtx, BlCtx, bv, nullptr, Vp);

    // attention middle (fp32)
    softmax_l_kernel<<<BB * CC, 256>>>(Kp);
    softmax_d_kernel<<<dim3(LL / 256, HH, BB), 256>>>(Qp);
    zero_ctx_kernel<<<(BB * HH * DD * DD) / 256, 256>>>(Cp);
    ctx_kernel<<<dim3(16, HH, BB), 128>>>(Kp, Vp, Cp);
    att_kernel<<<dim3(LL / 128, HH, BB), 128>>>(Qp, Cp, Ap);

    // output projection (+ residual)
    tconv_kernel<<<gT, dim3(32, 8)>>>(Ap, BhAtt, BlAtt);
    gemm_mma_kernel<<<gG, 256>>>(Wh + 3 * CC * CC, Wl + 3 * CC * CC,
                                 BhAtt, BlAtt, br, input_, out);
}

// round 5
// speedup vs baseline: 2.0286x; 1.1182x over previous
#include <cuda_runtime.h>
#include <cuda_bf16.h>
#include <math.h>
#include <float.h>
#include <stdint.h>

#define BB 8
#define CC 512
#define LL 8192
#define HH 8
#define DD 64

// ---------------------------------------------------------------------------
// Scratch (static device globals: allocation-free per harness rules)
// ---------------------------------------------------------------------------
static __device__ float g_Q[(size_t)BB * CC * LL];
static __device__ float g_K[(size_t)BB * CC * LL];
static __device__ float g_V[(size_t)BB * CC * LL];
static __device__ float g_CTX[BB * HH * DD * DD];

// transposed bf16 hi/lo operands: [B][L][C], C contiguous (K-contiguous for MMA B)
static __device__ __align__(256) __nv_bfloat16 g_Bh_in[(size_t)BB * LL * CC];
static __device__ __align__(256) __nv_bfloat16 g_Bl_in[(size_t)BB * LL * CC];
static __device__ __align__(256) __nv_bfloat16 g_Bh_ctx[(size_t)BB * LL * CC];
static __device__ __align__(256) __nv_bfloat16 g_Bl_ctx[(size_t)BB * LL * CC];
static __device__ __align__(256) __nv_bfloat16 g_Bh_att[(size_t)BB * LL * CC];
static __device__ __align__(256) __nv_bfloat16 g_Bl_att[(size_t)BB * LL * CC];
// weights bf16 hi/lo: 0=q 1=k 2=v 3=r   ([O][C] row-major, K-contiguous)
static __device__ __align__(256) __nv_bfloat16 g_Wh[4][CC * CC];
static __device__ __align__(256) __nv_bfloat16 g_Wl[4][CC * CC];

// ---------------------------------------------------------------------------
__device__ __forceinline__ uint32_t smem_u32(const void* p) {
    uint32_t a;
    asm("{ .reg .u64 t; cvta.to.shared.u64 t, %1; cvt.u32.u64 %0, t; }"
        : "=r"(a) : "l"(p));
    return a;
}
__device__ __forceinline__ void ldm_x4(uint32_t* r, uint32_t addr) {
    asm volatile("ldmatrix.sync.aligned.m8n8.x4.shared.b16 {%0,%1,%2,%3}, [%4];"
                 : "=r"(r[0]), "=r"(r[1]), "=r"(r[2]), "=r"(r[3]) : "r"(addr));
}
__device__ __forceinline__ void ldm_x2(uint32_t* r, uint32_t addr) {
    asm volatile("ldmatrix.sync.aligned.m8n8.x2.shared.b16 {%0,%1}, [%2];"
                 : "=r"(r[0]), "=r"(r[1]) : "r"(addr));
}
__device__ __forceinline__ void mma_bf16(float* d, const uint32_t* a, const uint32_t* b) {
    asm volatile(
        "mma.sync.aligned.m16n8k16.row.col.f32.bf16.bf16.f32 "
        "{%0,%1,%2,%3}, {%4,%5,%6,%7}, {%8,%9}, {%0,%1,%2,%3};"
        : "+f"(d[0]), "+f"(d[1]), "+f"(d[2]), "+f"(d[3])
        : "r"(a[0]), "r"(a[1]), "r"(a[2]), "r"(a[3]), "r"(b[0]), "r"(b[1]));
}
__device__ __forceinline__ void cp16(uint32_t dst, const void* src) {
    asm volatile("cp.async.ca.shared.global [%0], [%1], 16;"
                 :: "r"(dst), "l"(src) : "memory");
}

// ---------------------------------------------------------------------------
// Weight convert: fp32 [O,C] -> bf16 hi + lo
// ---------------------------------------------------------------------------
__global__ void wconv_kernel(const float* __restrict__ W,
                             __nv_bfloat16* __restrict__ Wh,
                             __nv_bfloat16* __restrict__ Wl)
{
    const int i = blockIdx.x * 256 + threadIdx.x;
    const float x = W[i];
    const __nv_bfloat16 hi = __float2bfloat16(x);
    Wh[i] = hi;
    Wl[i] = __float2bfloat16(x - __bfloat162float(hi));
}

// ---------------------------------------------------------------------------
// Transpose + split: X[b][c][l] fp32 -> XT[b][l][c] bf16 hi/lo
// grid (L/32, C/32, B), block (32, 8)
// ---------------------------------------------------------------------------
__global__ __launch_bounds__(256) void tconv_kernel(
    const float* __restrict__ X,
    __nv_bfloat16* __restrict__ Th, __nv_bfloat16* __restrict__ Tl)
{
    __shared__ float t[32][33];
    const int l0 = blockIdx.x * 32, c0 = blockIdx.y * 32, b = blockIdx.z;
    const float* xp = X + ((size_t)b * CC + c0) * LL + l0;
#pragma unroll
    for (int i = 0; i < 4; i++) {
        const int c = threadIdx.y + i * 8;
        t[c][threadIdx.x] = xp[(size_t)c * LL + threadIdx.x];
    }
    __syncthreads();
    __nv_bfloat16* th = Th + ((size_t)b * LL + l0) * CC + c0;
    __nv_bfloat16* tl = Tl + ((size_t)b * LL + l0) * CC + c0;
#pragma unroll
    for (int i = 0; i < 4; i++) {
        const int row = threadIdx.y + i * 8;
        const float v = t[threadIdx.x][row];
        const __nv_bfloat16 hi = __float2bfloat16(v);
        th[(size_t)row * CC + threadIdx.x] = hi;
        tl[(size_t)row * CC + threadIdx.x] =
            __float2bfloat16(v - __bfloat162float(hi));
    }
}

// ---------------------------------------------------------------------------
// mma.sync bf16 GEMM (3-term split), cp.async 2-stage pipeline:
//   Y[b, m0+m, n0+n] = sum_c A[m][c]*B[b][n][c] + bias (+resid)
// CTA tile M=128 N=128 K=32; 8 warps (2m x 4n); warp tile 64x32 (m16n8k16).
// smem rows padded to 40 halves (80B) -> conflict-free ldmatrix.
// ---------------------------------------------------------------------------
#define PADK 40
#define NCHUNK (CC / 32)
#define OFF_AL 10240
#define OFF_BH 20480
#define OFF_BL 30720
#define STAGE_B 40960
#define GEMM_DSM (2 * STAGE_B)

__global__ void __launch_bounds__(256, 2) gemm_mma_kernel(
    const __nv_bfloat16* __restrict__ Ah, const __nv_bfloat16* __restrict__ Al,
    const __nv_bfloat16* __restrict__ Bh, const __nv_bfloat16* __restrict__ Bl,
    const float* __restrict__ bias, const float* __restrict__ resid,
    float* __restrict__ Y)
{
    extern __shared__ char dsm[];
    const uint32_t sbase = smem_u32(dsm);

    const int tid = threadIdx.x, lane = tid & 31, wid = tid >> 5;
    const int wm = wid >> 2, wn = wid & 3;
    const int b = blockIdx.z;
    const int n0 = blockIdx.x * 128;
    const int m0 = blockIdx.y * 128;

    const __nv_bfloat16* Arh = Ah + (size_t)m0 * CC;
    const __nv_bfloat16* Arl = Al + (size_t)m0 * CC;
    const __nv_bfloat16* Brh = Bh + ((size_t)b * LL + n0) * CC;
    const __nv_bfloat16* Brl = Bl + ((size_t)b * LL + n0) * CC;

    // loader: i = tid + p*256 -> row = i>>2 (0..127), 16B group = i&3
    const int ldRow = tid >> 2;           // 0..63 (p=0), +64 (p=1)
    const int ldGrp = tid & 3;

    auto issue = [&](int kc) {
        const uint32_t sb = sbase + (uint32_t)(kc & 1) * STAGE_B;
        const size_t gc = (size_t)kc * 32 + ldGrp * 8;
#pragma unroll
        for (int p = 0; p < 2; p++) {
            const int row = ldRow + p * 64;
            const uint32_t so = sb + (uint32_t)(row * 80 + ldGrp * 16);
            const size_t go = (size_t)row * CC + gc;
            cp16(so, Arh + go);
            cp16(so + OFF_AL, Arl + go);
            cp16(so + OFF_BH, Brh + go);
            cp16(so + OFF_BL, Brl + go);
        }
        asm volatile("cp.async.commit_group;" ::: "memory");
    };

    float acc[4][4][4];
#pragma unroll
    for (int i = 0; i < 4; i++)
#pragma unroll
        for (int j = 0; j < 4; j++)
#pragma unroll
            for (int x = 0; x < 4; x++) acc[i][j][x] = 0.f;

    // ldmatrix smem byte offsets (relative to stage base)
    const uint32_t aRow = (uint32_t)(wm * 64) + (lane & 7) + (lane & 8);
    const uint32_t aKh = (lane & 16) >> 1;
    const uint32_t aOffB = (aRow * PADK + aKh) * 2;
    const uint32_t bRow = (uint32_t)(wn * 32) + (lane & 7);
    const uint32_t bKh = (uint32_t)(lane & 8);
    const uint32_t bOffB = (bRow * PADK + bKh) * 2;

    issue(0);

    for (int kc = 0; kc < NCHUNK; kc++) {
        asm volatile("cp.async.wait_group 0;" ::: "memory");
        __syncthreads();
        if (kc + 1 < NCHUNK) issue(kc + 1);

        const uint32_t stb = sbase + (uint32_t)(kc & 1) * STAGE_B;
#pragma unroll
        for (int ks = 0; ks < 2; ks++) {
            const uint32_t kb = ks * 32;
            uint32_t fbh[4][2], fbl[4][2];
#pragma unroll
            for (int nt = 0; nt < 4; nt++) {
                const uint32_t o = bOffB + nt * (8 * PADK * 2) + kb;
                ldm_x2(fbh[nt], stb + OFF_BH + o);
                ldm_x2(fbl[nt], stb + OFF_BL + o);
            }
#pragma unroll
            for (int mt = 0; mt < 4; mt++) {
                uint32_t fah[4], fal[4];
                const uint32_t o = aOffB + mt * (16 * PADK * 2) + kb;
                ldm_x4(fah, stb + o);
                ldm_x4(fal, stb + OFF_AL + o);
#pragma unroll
                for (int nt = 0; nt < 4; nt++) {
                    mma_bf16(acc[mt][nt], fah, fbh[nt]);
                    mma_bf16(acc[mt][nt], fah, fbl[nt]);
                    mma_bf16(acc[mt][nt], fal, fbh[nt]);
                }
            }
        }
    }

    // epilogue
    const int mbase = m0 + wm * 64 + (lane >> 2);
    const int nbase = n0 + wn * 32 + (lane & 3) * 2;
#pragma unroll
    for (int mt = 0; mt < 4; mt++) {
        const int m = mbase + mt * 16;
        const float bv0 = bias[m], bv1 = bias[m + 8];
        float* y0 = Y + ((size_t)b * CC + m) * LL;
        float* y1 = y0 + (size_t)8 * LL;
        const float* r0 = resid ? resid + ((size_t)b * CC + m) * LL : (const float*)0;
#pragma unroll
        for (int nt = 0; nt < 4; nt++) {
            const int n = nbase + nt * 8;
            float2 v0, v1;
            v0.x = acc[mt][nt][0] + bv0;
            v0.y = acc[mt][nt][1] + bv0;
            v1.x = acc[mt][nt][2] + bv1;
            v1.y = acc[mt][nt][3] + bv1;
            if (r0) {
                const float2 q0 = *(const float2*)(r0 + n);
                const float2 q1 = *(const float2*)(r0 + (size_t)8 * LL + n);
                v0.x += q0.x; v0.y += q0.y;
                v1.x += q1.x; v1.y += q1.y;
            }
            *(float2*)(y0 + n) = v0;
            *(float2*)(y1 + n) = v1;
        }
    }
}

// ---------------------------------------------------------------------------
// Softmax over L (axis=3): one block per (b, c) row.
// ---------------------------------------------------------------------------
__global__ __launch_bounds__(256) void softmax_l_kernel(float* __restrict__ P)
{
    float* p = P + (size_t)blockIdx.x * LL;
    const int tid = threadIdx.x;
    float v[LL / 256];
    float m = -FLT_MAX;
#pragma unroll
    for (int i = 0; i < LL / 256; i++) {
        v[i] = p[tid + i * 256];
        m = fmaxf(m, v[i]);
    }
    __shared__ float red[256];
    red[tid] = m; __syncthreads();
    for (int s = 128; s > 0; s >>= 1) {
        if (tid < s) red[tid] = fmaxf(red[tid], red[tid + s]);
        __syncthreads();
    }
    m = red[0];
    __syncthreads();
    float sum = 0.f;
#pragma unroll
    for (int i = 0; i < LL / 256; i++) {
        v[i] = __expf(v[i] - m);
        sum += v[i];
    }
    red[tid] = sum; __syncthreads();
    for (int s = 128; s > 0; s >>= 1) {
        if (tid < s) red[tid] += red[tid + s];
        __syncthreads();
    }
    const float inv = 1.f / red[0];
#pragma unroll
    for (int i = 0; i < LL / 256; i++) p[tid + i * 256] = v[i] * inv;
}

// ---------------------------------------------------------------------------
// Softmax over DK (axis=2).
// ---------------------------------------------------------------------------
__global__ __launch_bounds__(256) void softmax_d_kernel(float* __restrict__ P)
{
    const int l = blockIdx.x * 256 + threadIdx.x;
    float* p = P + ((size_t)blockIdx.z * CC + blockIdx.y * DD) * LL + l;
    float v[DD];
    float m = -FLT_MAX;
#pragma unroll
    for (int d = 0; d < DD; d++) {
        v[d] = p[(size_t)d * LL];
        m = fmaxf(m, v[d]);
    }
    float s = 0.f;
#pragma unroll
    for (int d = 0; d < DD; d++) {
        v[d] = __expf(v[d] - m);
        s += v[d];
    }
    const float inv = 1.f / s;
#pragma unroll
    for (int d = 0; d < DD; d++) p[(size_t)d * LL] = v[d] * inv;
}

__global__ void zero_ctx_kernel(float* __restrict__ C)
{
    C[blockIdx.x * 256 + threadIdx.x] = 0.f;
}

// ---------------------------------------------------------------------------
// ctx[b,h,dk,dv] = sum_l K[b,h*64+dk,l] * V[b,h*64+dv,l]
// ---------------------------------------------------------------------------
__global__ __launch_bounds__(128) void ctx_kernel(
    const float* __restrict__ Kk, const float* __restrict__ Vv,
    float* __restrict__ CTX)
{
    const int b = blockIdx.z, h = blockIdx.y;
    const int lStart = blockIdx.x * (LL / 16);
    const float* kp = Kk + ((size_t)b * CC + h * DD) * LL;
    const float* vp = Vv + ((size_t)b * CC + h * DD) * LL;

    __shared__ float ks[32][65];
    __shared__ float vs[32][65];

    const int dk0 = (threadIdx.x >> 4) * 8;
    const int dv0 = (threadIdx.x & 15) * 4;
    float acc[8][4];
#pragma unroll
    for (int i = 0; i < 8; i++)
#pragma unroll
        for (int j = 0; j < 4; j++) acc[i][j] = 0.f;

    for (int t = 0; t < LL / 16; t += 32) {
#pragma unroll
        for (int i = 0; i < 4; i++) {
            const int idx = threadIdx.x + i * 128;
            const int row = idx >> 3;
            const int col = (idx & 7) * 4;
            const float4 k4 = *(const float4*)(kp + (size_t)row * LL + lStart + t + col);
            ks[col + 0][row] = k4.x; ks[col + 1][row] = k4.y;
            ks[col + 2][row] = k4.z; ks[col + 3][row] = k4.w;
            const float4 v4 = *(const float4*)(vp + (size_t)row * LL + lStart + t + col);
            vs[col + 0][row] = v4.x; vs[col + 1][row] = v4.y;
            vs[col + 2][row] = v4.z; vs[col + 3][row] = v4.w;
        }
        __syncthreads();
#pragma unroll 8
        for (int ll = 0; ll < 32; ll++) {
            float a[8], bq[4];
#pragma unroll
            for (int i = 0; i < 8; i++) a[i] = ks[ll][dk0 + i];
#pragma unroll
            for (int j = 0; j < 4; j++) bq[j] = vs[ll][dv0 + j];
#pragma unroll
            for (int i = 0; i < 8; i++)
#pragma unroll
                for (int j = 0; j < 4; j++)
                    acc[i][j] = fmaf(a[i], bq[j], acc[i][j]);
        }
        __syncthreads();
    }

    float* cp = CTX + (size_t)(b * HH + h) * DD * DD;
#pragma unroll
    for (int i = 0; i < 8; i++)
#pragma unroll
        for (int j = 0; j < 4; j++)
            atomicAdd(&cp[(dk0 + i) * DD + dv0 + j], acc[i][j]);
}

// ---------------------------------------------------------------------------
// att: [b, h*64+dv, l] = sum_dk ctx[b,h,dk,dv] * Q[b, h*64+dk, l]
// Output written DIRECTLY as bf16 hi/lo in XT layout [b][l][c] for final GEMM.
// grid: (LL/128, HH, BB), 128 threads.
// ---------------------------------------------------------------------------
__global__ __launch_bounds__(128) void att_kernel(
    const float* __restrict__ Q, const float* __restrict__ CTX,
    __nv_bfloat16* __restrict__ Th, __nv_bfloat16* __restrict__ Tl)
{
    const int b = blockIdx.z, h = blockIdx.y;
    const int lBase = blockIdx.x * 128;

    __shared__ float cs[DD][DD];          // [dk][dv]
    __shared__ float stage[64][65];
    const float* cp = CTX + (size_t)(b * HH + h) * DD * DD;
    for (int i = threadIdx.x; i < DD * DD; i += 128)
        ((float*)cs)[i] = cp[i];
    __syncthreads();

    const int lane5 = threadIdx.x & 31;
    const int dv0 = (threadIdx.x >> 5) * 16;
    const int l0 = lBase + lane5 * 4;
    const float* qp = Q + ((size_t)b * CC + h * DD) * LL;

    float acc[16][4];
#pragma unroll
    for (int j = 0; j < 16; j++)
#pragma unroll
        for (int i = 0; i < 4; i++) acc[j][i] = 0.f;

#pragma unroll 4
    for (int dk = 0; dk < DD; dk++) {
        const float4 q4 = *(const float4*)(qp + (size_t)dk * LL + l0);
#pragma unroll
        for (int j = 0; j < 16; j++) {
            const float c = cs[dk][dv0 + j];
            acc[j][0] = fmaf(c, q4.x, acc[j][0]);
            acc[j][1] = fmaf(c, q4.y, acc[j][1]);
            acc[j][2] = fmaf(c, q4.z, acc[j][2]);
            acc[j][3] = fmaf(c, q4.w, acc[j][3]);
        }
    }

    // stage + write bf16 hi/lo to XT[b][l][c], two 64-row halves
#pragma unroll
    for (int half = 0; half < 2; half++) {
        __syncthreads();
        if ((lane5 >> 4) == half) {
            const int lr = (lane5 & 15) * 4;   // row within half
#pragma unroll
            for (int i = 0; i < 4; i++)
#pragma unroll
                for (int j = 0; j < 16; j++)
                    stage[lr + i][dv0 + j] = acc[j][i];
        }
        __syncthreads();
        const int r0 = threadIdx.x >> 2;       // 0..31
        const int sub = threadIdx.x & 3;
#pragma unroll
        for (int rr = 0; rr < 2; rr++) {
            const int r = r0 + rr * 32;
            __nv_bfloat16 hh[16], llo[16];
#pragma unroll
            for (int k = 0; k < 16; k++) {
                const float v = stage[r][sub * 16 + k];
                hh[k] = __float2bfloat16(v);
                llo[k] = __float2bfloat16(v - __bfloat162float(hh[k]));
            }
            const size_t o = ((size_t)b * LL + lBase + half * 64 + r) * CC
                             + h * DD + sub * 16;
            // 16 bf16 = 32 bytes: TWO uint4 stores (R4 bug: only one was stored)
            *(uint4*)(Th + o) = *(const uint4*)hh;
            *(uint4*)(Th + o + 8) = *(const uint4*)(hh + 8);
            *(uint4*)(Tl + o) = *(const uint4*)llo;
            *(uint4*)(Tl + o + 8) = *(const uint4*)(llo + 8);
        }
    }
}

// ---------------------------------------------------------------------------
extern "C" void kernel_launch(void* const* d_in, const int* in_sizes, int n_in,
                              void* d_out, int out_size)
{
    const float* input_ = (const float*)d_in[0];
    const float* context_ = (const float*)d_in[1];
    const float* Wk = (const float*)d_in[2];
    const float* bk = (const float*)d_in[3];
    const float* Wq = (const float*)d_in[4];
    const float* bq = (const float*)d_in[5];
    const float* Wv = (const float*)d_in[6];
    const float* bv = (const float*)d_in[7];
    const float* Wr = (const float*)d_in[8];
    const float* br = (const float*)d_in[9];
    float* out = (float*)d_out;

    float *Qp, *Kp, *Vp, *Cp;
    cudaGetSymbolAddress((void**)&Qp, g_Q);
    cudaGetSymbolAddress((void**)&Kp, g_K);
    cudaGetSymbolAddress((void**)&Vp, g_V);
    cudaGetSymbolAddress((void**)&Cp, g_CTX);

    __nv_bfloat16 *BhIn, *BlIn, *BhCtx, *BlCtx, *BhAtt, *BlAtt, *Wh, *Wl;
    cudaGetSymbolAddress((void**)&BhIn, g_Bh_in);
    cudaGetSymbolAddress((void**)&BlIn, g_Bl_in);
    cudaGetSymbolAddress((void**)&BhCtx, g_Bh_ctx);
    cudaGetSymbolAddress((void**)&BlCtx, g_Bl_ctx);
    cudaGetSymbolAddress((void**)&BhAtt, g_Bh_att);
    cudaGetSymbolAddress((void**)&BlAtt, g_Bl_att);
    cudaGetSymbolAddress((void**)&Wh, g_Wh);
    cudaGetSymbolAddress((void**)&Wl, g_Wl);

    static bool attr_set = false;
    if (!attr_set) {
        cudaFuncSetAttribute(gemm_mma_kernel,
                             cudaFuncAttributeMaxDynamicSharedMemorySize, GEMM_DSM);
        attr_set = true;
    }

    // weight conversions (0=q 1=k 2=v 3=r)
    wconv_kernel<<<CC * CC / 256, 256>>>(Wq, Wh + 0 * CC * CC, Wl + 0 * CC * CC);
    wconv_kernel<<<CC * CC / 256, 256>>>(Wk, Wh + 1 * CC * CC, Wl + 1 * CC * CC);
    wconv_kernel<<<CC * CC / 256, 256>>>(Wv, Wh + 2 * CC * CC, Wl + 2 * CC * CC);
    wconv_kernel<<<CC * CC / 256, 256>>>(Wr, Wh + 3 * CC * CC, Wl + 3 * CC * CC);

    // input transposes + bf16 split
    const dim3 gT(LL / 32, CC / 32, BB);
    tconv_kernel<<<gT, dim3(32, 8)>>>(input_, BhIn, BlIn);
    tconv_kernel<<<gT, dim3(32, 8)>>>(context_, BhCtx, BlCtx);

    // projections on tensor cores (mma.sync bf16, 3-term split, cp.async pipe)
    const dim3 gG(LL / 128, CC / 128, BB);
    gemm_mma_kernel<<<gG, 256, GEMM_DSM>>>(Wh + 0 * CC * CC, Wl + 0 * CC * CC,
                                           BhIn, BlIn, bq, nullptr, Qp);
    gemm_mma_kernel<<<gG, 256, GEMM_DSM>>>(Wh + 1 * CC * CC, Wl + 1 * CC * CC,
                                           BhCtx, BlCtx, bk, nullptr, Kp);
    gemm_mma_kernel<<<gG, 256, GEMM_DSM>>>(Wh + 2 * CC * CC, Wl + 2 * CC * CC,
                                           BhCtx, BlCtx, bv, nullptr, Vp);

    // attention middle (fp32), att writes bf16 hi/lo XT layout directly
    softmax_l_kernel<<<BB * CC, 256>>>(Kp);
    softmax_d_kernel<<<dim3(LL / 256, HH, BB), 256>>>(Qp);
    zero_ctx_kernel<<<(BB * HH * DD * DD) / 256, 256>>>(Cp);
    ctx_kernel<<<dim3(16, HH, BB), 128>>>(Kp, Vp, Cp);
    att_kernel<<<dim3(LL / 128, HH, BB), 128>>>(Qp, Cp, BhAtt, BlAtt);

    // output projection (+ residual)
    gemm_mma_kernel<<<gG, 256, GEMM_DSM>>>(Wh + 3 * CC * CC, Wl + 3 * CC * CC,
                                           BhAtt, BlAtt, br, input_, out);
}

// round 6
// speedup vs baseline: 3.8013x; 1.8739x over previous
#include <cuda_runtime.h>
#include <cuda_fp16.h>
#include <math.h>
#include <float.h>
#include <stdint.h>

#define BB 8
#define CC 512
#define LL 8192
#define HH 8
#define DD 64

// ---------------------------------------------------------------------------
// Scratch (static device globals: allocation-free per harness rules)
// ---------------------------------------------------------------------------
static __device__ float g_Q[(size_t)BB * CC * LL];
static __device__ float g_K[(size_t)BB * CC * LL];
static __device__ float g_V[(size_t)BB * CC * LL];
static __device__ float g_CTX[BB * HH * DD * DD];

// transposed fp16 operands: [B][L][C], C contiguous (K-contiguous for MMA B)
static __device__ __align__(256) __half g_X_in[(size_t)BB * LL * CC];
static __device__ __align__(256) __half g_X_ctx[(size_t)BB * LL * CC];
static __device__ __align__(256) __half g_X_att[(size_t)BB * LL * CC];
// weights fp16: 0=q 1=k 2=v 3=r   ([O][C] row-major, K-contiguous)
static __device__ __align__(256) __half g_W[4][CC * CC];

// ---------------------------------------------------------------------------
__device__ __forceinline__ uint32_t smem_u32(const void* p) {
    uint32_t a;
    asm("{ .reg .u64 t; cvta.to.shared.u64 t, %1; cvt.u32.u64 %0, t; }"
        : "=r"(a) : "l"(p));
    return a;
}
__device__ __forceinline__ void ldm_x4(uint32_t* r, uint32_t addr) {
    asm volatile("ldmatrix.sync.aligned.m8n8.x4.shared.b16 {%0,%1,%2,%3}, [%4];"
                 : "=r"(r[0]), "=r"(r[1]), "=r"(r[2]), "=r"(r[3]) : "r"(addr));
}
__device__ __forceinline__ void ldm_x2(uint32_t* r, uint32_t addr) {
    asm volatile("ldmatrix.sync.aligned.m8n8.x2.shared.b16 {%0,%1}, [%2];"
                 : "=r"(r[0]), "=r"(r[1]) : "r"(addr));
}
__device__ __forceinline__ void mma_f16(float* d, const uint32_t* a, const uint32_t* b) {
    asm volatile(
        "mma.sync.aligned.m16n8k16.row.col.f32.f16.f16.f32 "
        "{%0,%1,%2,%3}, {%4,%5,%6,%7}, {%8,%9}, {%0,%1,%2,%3};"
        : "+f"(d[0]), "+f"(d[1]), "+f"(d[2]), "+f"(d[3])
        : "r"(a[0]), "r"(a[1]), "r"(a[2]), "r"(a[3]), "r"(b[0]), "r"(b[1]));
}
__device__ __forceinline__ void cp16(uint32_t dst, const void* src) {
    asm volatile("cp.async.ca.shared.global [%0], [%1], 16;"
                 :: "r"(dst), "l"(src) : "memory");
}

// ---------------------------------------------------------------------------
// Weight convert: fp32 [O,C] -> fp16
// ---------------------------------------------------------------------------
__global__ void wconv_kernel(const float* __restrict__ W, __half* __restrict__ Wh)
{
    const int i = blockIdx.x * 256 + threadIdx.x;
    Wh[i] = __float2half(W[i]);
}

// ---------------------------------------------------------------------------
// Transpose + convert: X[b][c][l] fp32 -> XT[b][l][c] fp16
// grid (L/32, C/32, B), block (32, 8)
// ---------------------------------------------------------------------------
__global__ __launch_bounds__(256) void tconv_kernel(
    const float* __restrict__ X, __half* __restrict__ Th)
{
    __shared__ float t[32][33];
    const int l0 = blockIdx.x * 32, c0 = blockIdx.y * 32, b = blockIdx.z;
    const float* xp = X + ((size_t)b * CC + c0) * LL + l0;
#pragma unroll
    for (int i = 0; i < 4; i++) {
        const int c = threadIdx.y + i * 8;
        t[c][threadIdx.x] = xp[(size_t)c * LL + threadIdx.x];
    }
    __syncthreads();
    __half* th = Th + ((size_t)b * LL + l0) * CC + c0;
#pragma unroll
    for (int i = 0; i < 4; i++) {
        const int row = threadIdx.y + i * 8;
        th[(size_t)row * CC + threadIdx.x] = __float2half(t[threadIdx.x][row]);
    }
}

// ---------------------------------------------------------------------------
// mma.sync fp16 GEMM, cp.async 3-stage pipeline:
//   Y[b, m0+m, n0+n] = sum_c A[m][c]*B[b][n][c] + bias (+resid)
// CTA tile M=128 N=128 K=32; 8 warps (2m x 4n); warp tile 64x32 (m16n8k16).
// smem rows padded to 40 halves (80B) -> conflict-free ldmatrix.
// ---------------------------------------------------------------------------
#define PADK 40
#define NCHUNK (CC / 32)
#define OFF_B 10240
#define STAGE_B 20480
#define GEMM_DSM (3 * STAGE_B)

__global__ void __launch_bounds__(256, 2) gemm_mma_kernel(
    const __half* __restrict__ A, const __half* __restrict__ B,
    const float* __restrict__ bias, const float* __restrict__ resid,
    float* __restrict__ Y)
{
    extern __shared__ char dsm[];
    const uint32_t sbase = smem_u32(dsm);

    const int tid = threadIdx.x, lane = tid & 31, wid = tid >> 5;
    const int wm = wid >> 2, wn = wid & 3;
    const int b = blockIdx.z;
    const int n0 = blockIdx.x * 128;
    const int m0 = blockIdx.y * 128;

    const __half* Ar = A + (size_t)m0 * CC;
    const __half* Br = B + ((size_t)b * LL + n0) * CC;

    // loader: row = tid>>2 (+64), 16B group = tid&3
    const int ldRow = tid >> 2;
    const int ldGrp = tid & 3;

    auto issue = [&](int kc) {
        const uint32_t sb = sbase + (uint32_t)(kc % 3) * STAGE_B;
        const size_t gc = (size_t)kc * 32 + ldGrp * 8;
#pragma unroll
        for (int p = 0; p < 2; p++) {
            const int row = ldRow + p * 64;
            const uint32_t so = sb + (uint32_t)(row * 80 + ldGrp * 16);
            const size_t go = (size_t)row * CC + gc;
            cp16(so, Ar + go);
            cp16(so + OFF_B, Br + go);
        }
        asm volatile("cp.async.commit_group;" ::: "memory");
    };

    float acc[4][4][4];
#pragma unroll
    for (int i = 0; i < 4; i++)
#pragma unroll
        for (int j = 0; j < 4; j++)
#pragma unroll
            for (int x = 0; x < 4; x++) acc[i][j][x] = 0.f;

    // ldmatrix smem byte offsets (relative to stage base)
    const uint32_t aRow = (uint32_t)(wm * 64) + (lane & 7) + (lane & 8);
    const uint32_t aKh = (lane & 16) >> 1;
    const uint32_t aOffB = (aRow * PADK + aKh) * 2;
    const uint32_t bRow = (uint32_t)(wn * 32) + (lane & 7);
    const uint32_t bKh = (uint32_t)(lane & 8);
    const uint32_t bOffB = (bRow * PADK + bKh) * 2;

    issue(0);
    issue(1);

    for (int kc = 0; kc < NCHUNK; kc++) {
        if (kc + 1 < NCHUNK) {
            asm volatile("cp.async.wait_group 1;" ::: "memory");
        } else {
            asm volatile("cp.async.wait_group 0;" ::: "memory");
        }
        __syncthreads();
        if (kc + 2 < NCHUNK) issue(kc + 2);

        const uint32_t stb = sbase + (uint32_t)(kc % 3) * STAGE_B;
#pragma unroll
        for (int ks = 0; ks < 2; ks++) {
            const uint32_t kb = ks * 32;
            uint32_t fb[4][2];
#pragma unroll
            for (int nt = 0; nt < 4; nt++)
                ldm_x2(fb[nt], stb + OFF_B + bOffB + nt * (8 * PADK * 2) + kb);
#pragma unroll
            for (int mt = 0; mt < 4; mt++) {
                uint32_t fa[4];
                ldm_x4(fa, stb + aOffB + mt * (16 * PADK * 2) + kb);
#pragma unroll
                for (int nt = 0; nt < 4; nt++)
                    mma_f16(acc[mt][nt], fa, fb[nt]);
            }
        }
    }

    // epilogue
    const int mbase = m0 + wm * 64 + (lane >> 2);
    const int nbase = n0 + wn * 32 + (lane & 3) * 2;
#pragma unroll
    for (int mt = 0; mt < 4; mt++) {
        const int m = mbase + mt * 16;
        const float bv0 = bias[m], bv1 = bias[m + 8];
        float* y0 = Y + ((size_t)b * CC + m) * LL;
        float* y1 = y0 + (size_t)8 * LL;
        const float* r0 = resid ? resid + ((size_t)b * CC + m) * LL : (const float*)0;
#pragma unroll
        for (int nt = 0; nt < 4; nt++) {
            const int n = nbase + nt * 8;
            float2 v0, v1;
            v0.x = acc[mt][nt][0] + bv0;
            v0.y = acc[mt][nt][1] + bv0;
            v1.x = acc[mt][nt][2] + bv1;
            v1.y = acc[mt][nt][3] + bv1;
            if (r0) {
                const float2 q0 = *(const float2*)(r0 + n);
                const float2 q1 = *(const float2*)(r0 + (size_t)8 * LL + n);
                v0.x += q0.x; v0.y += q0.y;
                v1.x += q1.x; v1.y += q1.y;
            }
            *(float2*)(y0 + n) = v0;
            *(float2*)(y1 + n) = v1;
        }
    }
}

// ---------------------------------------------------------------------------
// Softmax over L (axis=3): one block per (b, c) row.
// ---------------------------------------------------------------------------
__global__ __launch_bounds__(256) void softmax_l_kernel(float* __restrict__ P)
{
    float* p = P + (size_t)blockIdx.x * LL;
    const int tid = threadIdx.x;
    float v[LL / 256];
    float m = -FLT_MAX;
#pragma unroll
    for (int i = 0; i < LL / 256; i++) {
        v[i] = p[tid + i * 256];
        m = fmaxf(m, v[i]);
    }
    __shared__ float red[256];
    red[tid] = m; __syncthreads();
    for (int s = 128; s > 0; s >>= 1) {
        if (tid < s) red[tid] = fmaxf(red[tid], red[tid + s]);
        __syncthreads();
    }
    m = red[0];
    __syncthreads();
    float sum = 0.f;
#pragma unroll
    for (int i = 0; i < LL / 256; i++) {
        v[i] = __expf(v[i] - m);
        sum += v[i];
    }
    red[tid] = sum; __syncthreads();
    for (int s = 128; s > 0; s >>= 1) {
        if (tid < s) red[tid] += red[tid + s];
        __syncthreads();
    }
    const float inv = 1.f / red[0];
#pragma unroll
    for (int i = 0; i < LL / 256; i++) p[tid + i * 256] = v[i] * inv;
}

__global__ void zero_ctx_kernel(float* __restrict__ C)
{
    C[blockIdx.x * 256 + threadIdx.x] = 0.f;
}

// ---------------------------------------------------------------------------
// ctx[b,h,dk,dv] = sum_l K[b,h*64+dk,l] * V[b,h*64+dv,l]
// ---------------------------------------------------------------------------
__global__ __launch_bounds__(128) void ctx_kernel(
    const float* __restrict__ Kk, const float* __restrict__ Vv,
    float* __restrict__ CTX)
{
    const int b = blockIdx.z, h = blockIdx.y;
    const int lStart = blockIdx.x * (LL / 16);
    const float* kp = Kk + ((size_t)b * CC + h * DD) * LL;
    const float* vp = Vv + ((size_t)b * CC + h * DD) * LL;

    __shared__ float ks[32][65];
    __shared__ float vs[32][65];

    const int dk0 = (threadIdx.x >> 4) * 8;
    const int dv0 = (threadIdx.x & 15) * 4;
    float acc[8][4];
#pragma unroll
    for (int i = 0; i < 8; i++)
#pragma unroll
        for (int j = 0; j < 4; j++) acc[i][j] = 0.f;

    for (int t = 0; t < LL / 16; t += 32) {
#pragma unroll
        for (int i = 0; i < 4; i++) {
            const int idx = threadIdx.x + i * 128;
            const int row = idx >> 3;
            const int col = (idx & 7) * 4;
            const float4 k4 = *(const float4*)(kp + (size_t)row * LL + lStart + t + col);
            ks[col + 0][row] = k4.x; ks[col + 1][row] = k4.y;
            ks[col + 2][row] = k4.z; ks[col + 3][row] = k4.w;
            const float4 v4 = *(const float4*)(vp + (size_t)row * LL + lStart + t + col);
            vs[col + 0][row] = v4.x; vs[col + 1][row] = v4.y;
            vs[col + 2][row] = v4.z; vs[col + 3][row] = v4.w;
        }
        __syncthreads();
#pragma unroll 8
        for (int ll = 0; ll < 32; ll++) {
            float a[8], bq[4];
#pragma unroll
            for (int i = 0; i < 8; i++) a[i] = ks[ll][dk0 + i];
#pragma unroll
            for (int j = 0; j < 4; j++) bq[j] = vs[ll][dv0 + j];
#pragma unroll
            for (int i = 0; i < 8; i++)
#pragma unroll
                for (int j = 0; j < 4; j++)
                    acc[i][j] = fmaf(a[i], bq[j], acc[i][j]);
        }
        __syncthreads();
    }

    float* cp = CTX + (size_t)(b * HH + h) * DD * DD;
#pragma unroll
    for (int i = 0; i < 8; i++)
#pragma unroll
        for (int j = 0; j < 4; j++)
            atomicAdd(&cp[(dk0 + i) * DD + dv0 + j], acc[i][j]);
}

// ---------------------------------------------------------------------------
// Fused att + softmax_d:
//   q = softmax over dk of Q[b, h*64+dk, l] (fused, 2 passes over dk)
//   att[b, h*64+dv, l] = sum_dk ctx[b,h,dk,dv] * q
// Output written DIRECTLY as fp16 in XT layout [b][l][c] for the final GEMM.
// grid: (LL/128, HH, BB), 128 threads.
// ---------------------------------------------------------------------------
__global__ __launch_bounds__(128) void att_kernel(
    const float* __restrict__ Q, const float* __restrict__ CTX,
    __half* __restrict__ Th)
{
    const int b = blockIdx.z, h = blockIdx.y;
    const int lBase = blockIdx.x * 128;

    __shared__ float cs[DD][DD];          // [dk][dv]
    __shared__ float stage[64][65];
    const float* cp = CTX + (size_t)(b * HH + h) * DD * DD;
    for (int i = threadIdx.x; i < DD * DD; i += 128)
        ((float*)cs)[i] = cp[i];
    __syncthreads();

    const int lane5 = threadIdx.x & 31;
    const int dv0 = (threadIdx.x >> 5) * 16;
    const int l0 = lBase + lane5 * 4;
    const float* qp = Q + ((size_t)b * CC + h * DD) * LL;

    // pass 1: max over dk per l
    float mx[4] = {-FLT_MAX, -FLT_MAX, -FLT_MAX, -FLT_MAX};
#pragma unroll 8
    for (int dk = 0; dk < DD; dk++) {
        const float4 q4 = *(const float4*)(qp + (size_t)dk * LL + l0);
        mx[0] = fmaxf(mx[0], q4.x);
        mx[1] = fmaxf(mx[1], q4.y);
        mx[2] = fmaxf(mx[2], q4.z);
        mx[3] = fmaxf(mx[3], q4.w);
    }

    // pass 2: exp, sum, and unnormalized accumulation
    float acc[16][4];
#pragma unroll
    for (int j = 0; j < 16; j++)
#pragma unroll
        for (int i = 0; i < 4; i++) acc[j][i] = 0.f;
    float sum[4] = {0.f, 0.f, 0.f, 0.f};

#pragma unroll 4
    for (int dk = 0; dk < DD; dk++) {
        const float4 q4 = *(const float4*)(qp + (size_t)dk * LL + l0);
        float e0 = __expf(q4.x - mx[0]);
        float e1 = __expf(q4.y - mx[1]);
        float e2 = __expf(q4.z - mx[2]);
        float e3 = __expf(q4.w - mx[3]);
        sum[0] += e0; sum[1] += e1; sum[2] += e2; sum[3] += e3;
#pragma unroll
        for (int j = 0; j < 16; j++) {
            const float c = cs[dk][dv0 + j];
            acc[j][0] = fmaf(c, e0, acc[j][0]);
            acc[j][1] = fmaf(c, e1, acc[j][1]);
            acc[j][2] = fmaf(c, e2, acc[j][2]);
            acc[j][3] = fmaf(c, e3, acc[j][3]);
        }
    }
    const float inv0 = 1.f / sum[0], inv1 = 1.f / sum[1];
    const float inv2 = 1.f / sum[2], inv3 = 1.f / sum[3];
#pragma unroll
    for (int j = 0; j < 16; j++) {
        acc[j][0] *= inv0; acc[j][1] *= inv1;
        acc[j][2] *= inv2; acc[j][3] *= inv3;
    }

    // stage + write fp16 to XT[b][l][c], two 64-row halves
#pragma unroll
    for (int half_i = 0; half_i < 2; half_i++) {
        __syncthreads();
        if ((lane5 >> 4) == half_i) {
            const int lr = (lane5 & 15) * 4;
#pragma unroll
            for (int i = 0; i < 4; i++)
#pragma unroll
                for (int j = 0; j < 16; j++)
                    stage[lr + i][dv0 + j] = acc[j][i];
        }
        __syncthreads();
        const int r0 = threadIdx.x >> 2;       // 0..31
        const int sub = threadIdx.x & 3;
#pragma unroll
        for (int rr = 0; rr < 2; rr++) {
            const int r = r0 + rr * 32;
            __half hh[16];
#pragma unroll
            for (int k = 0; k < 16; k++)
                hh[k] = __float2half(stage[r][sub * 16 + k]);
            const size_t o = ((size_t)b * LL + lBase + half_i * 64 + r) * CC
                             + h * DD + sub * 16;
            *(uint4*)(Th + o) = *(const uint4*)hh;
            *(uint4*)(Th + o + 8) = *(const uint4*)(hh + 8);
        }
    }
}

// ---------------------------------------------------------------------------
extern "C" void kernel_launch(void* const* d_in, const int* in_sizes, int n_in,
                              void* d_out, int out_size)
{
    const float* input_ = (const float*)d_in[0];
    const float* context_ = (const float*)d_in[1];
    const float* Wk = (const float*)d_in[2];
    const float* bk = (const float*)d_in[3];
    const float* Wq = (const float*)d_in[4];
    const float* bq = (const float*)d_in[5];
    const float* Wv = (const float*)d_in[6];
    const float* bv = (const float*)d_in[7];
    const float* Wr = (const float*)d_in[8];
    const float* br = (const float*)d_in[9];
    float* out = (float*)d_out;

    float *Qp, *Kp, *Vp, *Cp;
    cudaGetSymbolAddress((void**)&Qp, g_Q);
    cudaGetSymbolAddress((void**)&Kp, g_K);
    cudaGetSymbolAddress((void**)&Vp, g_V);
    cudaGetSymbolAddress((void**)&Cp, g_CTX);

    __half *Xin, *Xctx, *Xatt, *Wp;
    cudaGetSymbolAddress((void**)&Xin, g_X_in);
    cudaGetSymbolAddress((void**)&Xctx, g_X_ctx);
    cudaGetSymbolAddress((void**)&Xatt, g_X_att);
    cudaGetSymbolAddress((void**)&Wp, g_W);

    static bool attr_set = false;
    if (!attr_set) {
        cudaFuncSetAttribute(gemm_mma_kernel,
                             cudaFuncAttributeMaxDynamicSharedMemorySize, GEMM_DSM);
        attr_set = true;
    }

    // weight conversions (0=q 1=k 2=v 3=r)
    wconv_kernel<<<CC * CC / 256, 256>>>(Wq, Wp + 0 * CC * CC);
    wconv_kernel<<<CC * CC / 256, 256>>>(Wk, Wp + 1 * CC * CC);
    wconv_kernel<<<CC * CC / 256, 256>>>(Wv, Wp + 2 * CC * CC);
    wconv_kernel<<<CC * CC / 256, 256>>>(Wr, Wp + 3 * CC * CC);

    // input transposes + fp16 convert
    const dim3 gT(LL / 32, CC / 32, BB);
    tconv_kernel<<<gT, dim3(32, 8)>>>(input_, Xin);
    tconv_kernel<<<gT, dim3(32, 8)>>>(context_, Xctx);

    // projections (mma.sync fp16, 3-stage cp.async pipe)
    const dim3 gG(LL / 128, CC / 128, BB);
    gemm_mma_kernel<<<gG, 256, GEMM_DSM>>>(Wp + 0 * CC * CC, Xin, bq, nullptr, Qp);
    gemm_mma_kernel<<<gG, 256, GEMM_DSM>>>(Wp + 1 * CC * CC, Xctx, bk, nullptr, Kp);
    gemm_mma_kernel<<<gG, 256, GEMM_DSM>>>(Wp + 2 * CC * CC, Xctx, bv, nullptr, Vp);

    // attention middle; att fuses softmax over dk + fp16 XT-layout output
    softmax_l_kernel<<<BB * CC, 256>>>(Kp);
    zero_ctx_kernel<<<(BB * HH * DD * DD) / 256, 256>>>(Cp);
    ctx_kernel<<<dim3(16, HH, BB), 128>>>(Kp, Vp, Cp);
    att_kernel<<<dim3(LL / 128, HH, BB), 128>>>(Qp, Cp, Xatt);

    // output projection (+ residual)
    gemm_mma_kernel<<<gG, 256, GEMM_DSM>>>(Wp + 3 * CC * CC, Xatt, br, input_, out);
}